// round 1
// baseline (speedup 1.0000x reference)
#include <cuda_runtime.h>
#include <math.h>

#define B_  2
#define S_  2048
#define H_  16
#define DN_ 128
#define DR_ 64
#define D_  192
#define DV_ 128
#define BM  64
#define BN  64
#define LD  68     // padded row stride for Qt/Kt/Ps (floats)
#define VLD 132    // padded row stride for Vs (floats)

// Scratch for preprocessed Q (scaled, rope applied) and K (rope applied, pe broadcast)
__device__ float g_Q[B_*S_*H_*D_];
__device__ float g_K[B_*S_*H_*D_];

__global__ void prep_q(const float* __restrict__ qn, const float* __restrict__ qp){
    int idx = blockIdx.x*blockDim.x + threadIdx.x;
    const int total = B_*S_*H_*D_;
    if (idx >= total) return;
    int d = idx % D_;
    int h = (idx / D_) % H_;
    int s = (idx / (D_*H_)) % S_;
    int b =  idx / (D_*H_*S_);
    const float scale = rsqrtf((float)(DN_+DR_));
    float val;
    if (d < DN_) {
        val = qn[(((size_t)(b*S_+s)*H_)+h)*DN_ + d];
    } else {
        int i = d - DN_;
        int j = (i < 32) ? i : i - 32;
        float invf = __expf(-(float)j * (logf(10000.0f)/32.0f));
        float ang  = (float)s * invf;
        float sn, cs; sincosf(ang, &sn, &cs);
        const float* pe = qp + (((size_t)(b*S_+s)*H_)+h)*DR_;
        val = (i < 32) ? (pe[i]*cs - pe[i+32]*sn)
                       : (pe[i]*cs + pe[i-32]*sn);
    }
    g_Q[idx] = val * scale;
}

__global__ void prep_k(const float* __restrict__ kn, const float* __restrict__ kp){
    int idx = blockIdx.x*blockDim.x + threadIdx.x;
    const int total = B_*S_*H_*D_;
    if (idx >= total) return;
    int d = idx % D_;
    int h = (idx / D_) % H_;
    int s = (idx / (D_*H_)) % S_;
    int b =  idx / (D_*H_*S_);
    float val;
    if (d < DN_) {
        val = kn[(((size_t)(b*S_+s)*H_)+h)*DN_ + d];
    } else {
        int i = d - DN_;
        int j = (i < 32) ? i : i - 32;
        float invf = __expf(-(float)j * (logf(10000.0f)/32.0f));
        float ang  = (float)s * invf;
        float sn, cs; sincosf(ang, &sn, &cs);
        const float* pe = kp + (size_t)(b*S_+s)*DR_;   // k_pe has H=1
        val = (i < 32) ? (pe[i]*cs - pe[i+32]*sn)
                       : (pe[i]*cs + pe[i-32]*sn);
    }
    g_K[idx] = val;
}

__global__ __launch_bounds__(256, 1)
void attn(const float* __restrict__ V, float* __restrict__ O, float* __restrict__ LSE){
    extern __shared__ float sm[];
    float* Qt = sm;                 // [D_][LD] transposed Q tile
    float* Kt = Qt + D_*LD;         // [D_][LD] transposed K tile
    float* Vs = Kt + D_*LD;         // [BN][VLD]
    float* Ps = Vs + BN*VLD;        // [BM][LD]

    int mtile = gridDim.x - 1 - blockIdx.x;   // big CTAs first
    int bh = blockIdx.y;
    int b = bh / H_, h = bh % H_;
    int m0 = mtile * BM;
    int tid = threadIdx.x;
    int tr = tid >> 4, tc = tid & 15;
    int r0 = tr*4, c0 = tc*4, v0 = tc*8;

    // Load Q tile transposed (coalesced global, conflict-light smem)
    for (int i = tid; i < BM*D_; i += 256) {
        int d = i % D_, r = i / D_;
        Qt[d*LD + r] = g_Q[(((size_t)(b*S_ + m0 + r)*H_) + h)*D_ + d];
    }

    float m_i[4], l_i[4], o_acc[4][8];
    #pragma unroll
    for (int i = 0; i < 4; i++) {
        m_i[i] = -INFINITY; l_i[i] = 0.f;
        #pragma unroll
        for (int k = 0; k < 8; k++) o_acc[i][k] = 0.f;
    }

    for (int j = 0; j <= mtile; j++) {
        int n0 = j * BN;
        __syncthreads();   // previous iteration done with Kt/Vs/Ps
        for (int i = tid; i < BN*D_; i += 256) {
            int d = i % D_, n = i / D_;
            Kt[d*LD + n] = g_K[(((size_t)(b*S_ + n0 + n)*H_) + h)*D_ + d];
        }
        for (int i = tid; i < BN*DV_; i += 256) {
            int d = i % DV_, n = i / DV_;
            Vs[n*VLD + d] = V[(((size_t)(b*S_ + n0 + n)*H_) + h)*DV_ + d];
        }
        __syncthreads();

        // ---- S = Q @ K^T (4x4 per thread) ----
        float acc[4][4];
        #pragma unroll
        for (int i = 0; i < 4; i++)
            #pragma unroll
            for (int c = 0; c < 4; c++) acc[i][c] = 0.f;

        #pragma unroll 4
        for (int kk = 0; kk < D_; kk++) {
            float4 a  = *(const float4*)&Qt[kk*LD + r0];
            float4 bb = *(const float4*)&Kt[kk*LD + c0];
            acc[0][0] += a.x*bb.x; acc[0][1] += a.x*bb.y; acc[0][2] += a.x*bb.z; acc[0][3] += a.x*bb.w;
            acc[1][0] += a.y*bb.x; acc[1][1] += a.y*bb.y; acc[1][2] += a.y*bb.z; acc[1][3] += a.y*bb.w;
            acc[2][0] += a.z*bb.x; acc[2][1] += a.z*bb.y; acc[2][2] += a.z*bb.z; acc[2][3] += a.z*bb.w;
            acc[3][0] += a.w*bb.x; acc[3][1] += a.w*bb.y; acc[3][2] += a.w*bb.z; acc[3][3] += a.w*bb.w;
        }

        if (j == mtile) {   // causal mask only on diagonal tile
            #pragma unroll
            for (int i = 0; i < 4; i++)
                #pragma unroll
                for (int c = 0; c < 4; c++)
                    if (n0 + c0 + c > m0 + r0 + i) acc[i][c] = -INFINITY;
        }

        // ---- online softmax (row groups = 16 lanes sharing tr) ----
        #pragma unroll
        for (int i = 0; i < 4; i++) {
            float mx = fmaxf(fmaxf(acc[i][0], acc[i][1]), fmaxf(acc[i][2], acc[i][3]));
            mx = fmaxf(mx, __shfl_xor_sync(0xffffffffu, mx, 1));
            mx = fmaxf(mx, __shfl_xor_sync(0xffffffffu, mx, 2));
            mx = fmaxf(mx, __shfl_xor_sync(0xffffffffu, mx, 4));
            mx = fmaxf(mx, __shfl_xor_sync(0xffffffffu, mx, 8));
            float mnew = fmaxf(m_i[i], mx);
            float corr = __expf(m_i[i] - mnew);
            float ssum = 0.f;
            #pragma unroll
            for (int c = 0; c < 4; c++) {
                float p = __expf(acc[i][c] - mnew);
                Ps[(r0+i)*LD + c0 + c] = p;
                ssum += p;
            }
            ssum += __shfl_xor_sync(0xffffffffu, ssum, 1);
            ssum += __shfl_xor_sync(0xffffffffu, ssum, 2);
            ssum += __shfl_xor_sync(0xffffffffu, ssum, 4);
            ssum += __shfl_xor_sync(0xffffffffu, ssum, 8);
            l_i[i] = l_i[i]*corr + ssum;
            m_i[i] = mnew;
            #pragma unroll
            for (int k = 0; k < 8; k++) o_acc[i][k] *= corr;
        }
        __syncthreads();   // Ps visible to all

        // ---- O += P @ V (4x8 per thread) ----
        #pragma unroll 4
        for (int n = 0; n < BN; n++) {
            float p0 = Ps[(r0+0)*LD + n];
            float p1 = Ps[(r0+1)*LD + n];
            float p2 = Ps[(r0+2)*LD + n];
            float p3 = Ps[(r0+3)*LD + n];
            float4 va = *(const float4*)&Vs[n*VLD + v0];
            float4 vb = *(const float4*)&Vs[n*VLD + v0 + 4];
            o_acc[0][0] += p0*va.x; o_acc[0][1] += p0*va.y; o_acc[0][2] += p0*va.z; o_acc[0][3] += p0*va.w;
            o_acc[0][4] += p0*vb.x; o_acc[0][5] += p0*vb.y; o_acc[0][6] += p0*vb.z; o_acc[0][7] += p0*vb.w;
            o_acc[1][0] += p1*va.x; o_acc[1][1] += p1*va.y; o_acc[1][2] += p1*va.z; o_acc[1][3] += p1*va.w;
            o_acc[1][4] += p1*vb.x; o_acc[1][5] += p1*vb.y; o_acc[1][6] += p1*vb.z; o_acc[1][7] += p1*vb.w;
            o_acc[2][0] += p2*va.x; o_acc[2][1] += p2*va.y; o_acc[2][2] += p2*va.z; o_acc[2][3] += p2*va.w;
            o_acc[2][4] += p2*vb.x; o_acc[2][5] += p2*vb.y; o_acc[2][6] += p2*vb.z; o_acc[2][7] += p2*vb.w;
            o_acc[3][0] += p3*va.x; o_acc[3][1] += p3*va.y; o_acc[3][2] += p3*va.z; o_acc[3][3] += p3*va.w;
            o_acc[3][4] += p3*vb.x; o_acc[3][5] += p3*vb.y; o_acc[3][6] += p3*vb.z; o_acc[3][7] += p3*vb.w;
        }
    }

    // ---- epilogue ----
    #pragma unroll
    for (int i = 0; i < 4; i++) {
        float inv = 1.0f / l_i[i];
        int row = m0 + r0 + i;
        float* dst = O + (((size_t)(b*S_+row)*H_) + h)*DV_ + v0;
        float4 wa, wb;
        wa.x = o_acc[i][0]*inv; wa.y = o_acc[i][1]*inv; wa.z = o_acc[i][2]*inv; wa.w = o_acc[i][3]*inv;
        wb.x = o_acc[i][4]*inv; wb.y = o_acc[i][5]*inv; wb.z = o_acc[i][6]*inv; wb.w = o_acc[i][7]*inv;
        *(float4*)dst = wa;
        *(float4*)(dst + 4) = wb;
        if (tc == 0)
            LSE[(size_t)(b*S_+row)*H_ + h] = (m_i[i] + logf(l_i[i])) * 1.4426950408889634f;
    }
}

extern "C" void kernel_launch(void* const* d_in, const int* in_sizes, int n_in,
                              void* d_out, int out_size) {
    const float* q_nope = (const float*)d_in[0];
    const float* q_pe   = (const float*)d_in[1];
    const float* k_nope = (const float*)d_in[2];
    const float* k_pe   = (const float*)d_in[3];
    const float* v      = (const float*)d_in[4];
    float* out = (float*)d_out;
    float* o_out   = out;
    float* lse_out = out + (size_t)B_*S_*H_*DV_;

    const int total = B_*S_*H_*D_;
    prep_q<<<(total + 255)/256, 256>>>(q_nope, q_pe);
    prep_k<<<(total + 255)/256, 256>>>(k_nope, k_pe);

    const size_t smem = (size_t)(D_*LD*2 + BN*VLD + BM*LD) * sizeof(float);
    cudaFuncSetAttribute(attn, cudaFuncAttributeMaxDynamicSharedMemorySize, (int)smem);
    dim3 grid(S_/BM, B_*H_);
    attn<<<grid, 256, smem>>>(v, o_out, lse_out);
}

// round 3
// speedup vs baseline: 4.4304x; 4.4304x over previous
#include <cuda_runtime.h>
#include <cuda_fp16.h>
#include <cstdint>
#include <math.h>

#define B_  2
#define S_  2048
#define H_  16
#define DN_ 128
#define DR_ 64
#define D_  192
#define DV_ 128
#define BM  128
#define BN  64

#define QLD 200   // halfs per row (Q/K tiles)
#define VLD 136
#define PLD 72

#define SQ_OFF 0
#define SK_OFF (128*QLD*2)                  // 51200
#define SV_OFF (SK_OFF + 64*QLD*2)          // 76800
#define SP_OFF (SV_OFF + 64*VLD*2)          // 94208
#define SMEM_TOTAL (SP_OFF + 128*PLD*2)     // 112640

// ---- scratch (prepped fp16 operands) ----
__device__ __half  g_Qh[(size_t)B_*S_*H_*D_];
__device__ __half  g_Kh[(size_t)B_*S_*H_*D_];
__device__ __half  g_Vh[(size_t)B_*S_*H_*DV_];
__device__ float2  g_cs[S_*32];

// ---- helpers ----
__device__ __forceinline__ uint32_t smem_u32(const void* p){
    uint32_t a;
    asm("{ .reg .u64 t; cvta.to.shared.u64 t, %1; cvt.u32.u64 %0, t; }" : "=r"(a) : "l"(p));
    return a;
}
__device__ __forceinline__ void ldsm4(uint32_t& r0, uint32_t& r1, uint32_t& r2, uint32_t& r3, uint32_t a){
    asm volatile("ldmatrix.sync.aligned.m8n8.x4.shared.b16 {%0,%1,%2,%3},[%4];"
        : "=r"(r0),"=r"(r1),"=r"(r2),"=r"(r3) : "r"(a));
}
__device__ __forceinline__ void ldsm4t(uint32_t& r0, uint32_t& r1, uint32_t& r2, uint32_t& r3, uint32_t a){
    asm volatile("ldmatrix.sync.aligned.m8n8.x4.trans.shared.b16 {%0,%1,%2,%3},[%4];"
        : "=r"(r0),"=r"(r1),"=r"(r2),"=r"(r3) : "r"(a));
}
__device__ __forceinline__ void mma16816(float* c, uint32_t a0, uint32_t a1, uint32_t a2, uint32_t a3,
                                         uint32_t b0, uint32_t b1){
    asm volatile("mma.sync.aligned.m16n8k16.row.col.f32.f16.f16.f32 "
        "{%0,%1,%2,%3},{%4,%5,%6,%7},{%8,%9},{%0,%1,%2,%3};"
        : "+f"(c[0]),"+f"(c[1]),"+f"(c[2]),"+f"(c[3])
        : "r"(a0),"r"(a1),"r"(a2),"r"(a3),"r"(b0),"r"(b1));
}

// ---- prep ----
__global__ void k_cs(){
    int i = blockIdx.x*256 + threadIdx.x;
    if (i >= S_*32) return;
    int s = i >> 5, j = i & 31;
    float inv = __expf(-(float)j * (logf(10000.0f)/32.0f));
    float ang = (float)s * inv;
    float sn, cs; sincosf(ang, &sn, &cs);
    g_cs[i] = make_float2(cs, sn);
}

#define NQ_ (B_*S_*H_*D_)
#define NV_ (B_*S_*H_*DV_)
__global__ void k_prep(const float* __restrict__ qn, const float* __restrict__ qp,
                       const float* __restrict__ kn, const float* __restrict__ kp,
                       const float* __restrict__ v){
    int i = blockIdx.x*256 + threadIdx.x;
    const float scale = rsqrtf((float)(DN_+DR_));
    if (i < NQ_){
        int d = i % D_;
        int h = (i / D_) & 15;
        int s = (i / (D_*H_)) & 2047;
        int b =  i / (D_*H_*S_);
        float val;
        if (d < DN_) val = qn[(((size_t)(b*S_+s)*H_)+h)*DN_ + d];
        else {
            int r = d - DN_;
            int j = (r < 32) ? r : r - 32;
            float2 cs = g_cs[(s<<5)+j];
            const float* pe = qp + (((size_t)(b*S_+s)*H_)+h)*DR_;
            val = (r < 32) ? (pe[r]*cs.x - pe[r+32]*cs.y)
                           : (pe[r]*cs.x + pe[r-32]*cs.y);
        }
        g_Qh[i] = __float2half_rn(val * scale);
    } else if (i < 2*NQ_){
        int k = i - NQ_;
        int d = k % D_;
        int h = (k / D_) & 15;
        int s = (k / (D_*H_)) & 2047;
        int b =  k / (D_*H_*S_);
        float val;
        if (d < DN_) val = kn[(((size_t)(b*S_+s)*H_)+h)*DN_ + d];
        else {
            int r = d - DN_;
            int j = (r < 32) ? r : r - 32;
            float2 cs = g_cs[(s<<5)+j];
            const float* pe = kp + ((size_t)(b*S_+s))*DR_;
            val = (r < 32) ? (pe[r]*cs.x - pe[r+32]*cs.y)
                           : (pe[r]*cs.x + pe[r-32]*cs.y);
        }
        g_Kh[k] = __float2half_rn(val);
    } else {
        int k = i - 2*NQ_;
        if (k < NV_) g_Vh[k] = __float2half_rn(v[k]);
    }
}

// ---- attention ----
__global__ __launch_bounds__(256)
void attn(float* __restrict__ O, float* __restrict__ LSE)
{
    extern __shared__ char smem[];
    __half* smh = (__half*)smem;
    uint32_t sb = smem_u32(smem);
    const uint32_t sQ = sb + SQ_OFF, sK = sb + SK_OFF, sV = sb + SV_OFF, sP = sb + SP_OFF;

    int tid  = threadIdx.x;
    int lane = tid & 31;
    int wid  = tid >> 5;
    int t  = (int)gridDim.x - 1 - (int)blockIdx.x;
    int bh = blockIdx.y;
    int b = bh >> 4, h = bh & 15;
    int m0 = t * BM;
    int nt = 2*t + 2;
    int rw0 = wid * 16;

    // Q tile (once)
    for (int i = tid; i < 128*24; i += 256){
        int r = i / 24, c = (i % 24) * 8;
        *(uint4*)(smh + r*QLD + c) =
            *(const uint4*)(g_Qh + ((size_t)((b*S_+m0+r)*H_+h))*D_ + c);
    }
    __syncthreads();

    float o[16][4];
    #pragma unroll
    for (int d = 0; d < 16; d++){ o[d][0]=0.f; o[d][1]=0.f; o[d][2]=0.f; o[d][3]=0.f; }
    float m0r = -INFINITY, m1r = -INFINITY, l0 = 0.f, l1 = 0.f;

    int row0 = m0 + rw0 + (lane >> 2);
    int row1 = row0 + 8;

    for (int j = 0; j < nt; j++){
        int n0 = j * BN;
        if (j) __syncthreads();
        // K tile
        for (int i = tid; i < 64*24; i += 256){
            int r = i / 24, c = (i % 24) * 8;
            *(uint4*)(smh + (SK_OFF/2) + r*QLD + c) =
                *(const uint4*)(g_Kh + ((size_t)((b*S_+n0+r)*H_+h))*D_ + c);
        }
        // V tile
        for (int i = tid; i < 64*16; i += 256){
            int r = i / 16, c = (i % 16) * 8;
            *(uint4*)(smh + (SV_OFF/2) + r*VLD + c) =
                *(const uint4*)(g_Vh + ((size_t)((b*S_+n0+r)*H_+h))*DV_ + c);
        }
        __syncthreads();

        // ---- S = Q K^T ----
        float c_[8][4];
        #pragma unroll
        for (int q = 0; q < 8; q++){ c_[q][0]=0.f; c_[q][1]=0.f; c_[q][2]=0.f; c_[q][3]=0.f; }

        #pragma unroll
        for (int kc = 0; kc < 12; kc++){
            uint32_t a0,a1,a2,a3;
            ldsm4(a0,a1,a2,a3, sQ + (uint32_t)(((rw0 + (lane&15))*QLD + kc*16 + ((lane>>4)<<3))*2));
            #pragma unroll
            for (int np = 0; np < 4; np++){
                uint32_t b0,b1,b2,b3;
                int brow = np*16 + ((lane>>4)<<3) + (lane&7);
                int bcol = kc*16 + (((lane>>3)&1)<<3);
                ldsm4(b0,b1,b2,b3, sK + (uint32_t)((brow*QLD + bcol)*2));
                mma16816(c_[np*2+0], a0,a1,a2,a3, b0,b1);
                mma16816(c_[np*2+1], a0,a1,a2,a3, b2,b3);
            }
        }

        // ---- mask (only diagonal region tiles) ----
        if (j >= 2*t){
            int colb = n0 + (lane&3)*2;
            #pragma unroll
            for (int q = 0; q < 8; q++){
                int c0 = colb + q*8, c1 = c0 + 1;
                if (c0 > row0) c_[q][0] = -INFINITY;
                if (c1 > row0) c_[q][1] = -INFINITY;
                if (c0 > row1) c_[q][2] = -INFINITY;
                if (c1 > row1) c_[q][3] = -INFINITY;
            }
        }

        // ---- online softmax ----
        float mx0 = -INFINITY, mx1 = -INFINITY;
        #pragma unroll
        for (int q = 0; q < 8; q++){
            mx0 = fmaxf(mx0, fmaxf(c_[q][0], c_[q][1]));
            mx1 = fmaxf(mx1, fmaxf(c_[q][2], c_[q][3]));
        }
        mx0 = fmaxf(mx0, __shfl_xor_sync(0xffffffffu, mx0, 1));
        mx0 = fmaxf(mx0, __shfl_xor_sync(0xffffffffu, mx0, 2));
        mx1 = fmaxf(mx1, __shfl_xor_sync(0xffffffffu, mx1, 1));
        mx1 = fmaxf(mx1, __shfl_xor_sync(0xffffffffu, mx1, 2));
        float mn0 = fmaxf(m0r, mx0), mn1 = fmaxf(m1r, mx1);
        float corr0 = __expf(m0r - mn0), corr1 = __expf(m1r - mn1);
        m0r = mn0; m1r = mn1;

        float sum0 = 0.f, sum1 = 0.f;
        int pc = (lane&3)*2;
        #pragma unroll
        for (int q = 0; q < 8; q++){
            float p00 = __expf(c_[q][0] - mn0);
            float p01 = __expf(c_[q][1] - mn0);
            float p10 = __expf(c_[q][2] - mn1);
            float p11 = __expf(c_[q][3] - mn1);
            sum0 += p00 + p01; sum1 += p10 + p11;
            *(__half2*)(smh + (SP_OFF/2) + (rw0 + (lane>>2))*PLD + q*8 + pc)     = __floats2half2_rn(p00, p01);
            *(__half2*)(smh + (SP_OFF/2) + (rw0 + (lane>>2) + 8)*PLD + q*8 + pc) = __floats2half2_rn(p10, p11);
        }
        sum0 += __shfl_xor_sync(0xffffffffu, sum0, 1);
        sum0 += __shfl_xor_sync(0xffffffffu, sum0, 2);
        sum1 += __shfl_xor_sync(0xffffffffu, sum1, 1);
        sum1 += __shfl_xor_sync(0xffffffffu, sum1, 2);
        l0 = l0*corr0 + sum0;
        l1 = l1*corr1 + sum1;

        #pragma unroll
        for (int d = 0; d < 16; d++){
            o[d][0] *= corr0; o[d][1] *= corr0;
            o[d][2] *= corr1; o[d][3] *= corr1;
        }
        __syncthreads();

        // ---- O += P V ----
        #pragma unroll
        for (int kc = 0; kc < 4; kc++){
            uint32_t a0,a1,a2,a3;
            ldsm4(a0,a1,a2,a3, sP + (uint32_t)(((rw0 + (lane&15))*PLD + kc*16 + ((lane>>4)<<3))*2));
            #pragma unroll
            for (int dp = 0; dp < 8; dp++){
                uint32_t b0,b1,b2,b3;
                int brow = kc*16 + (((lane>>3)&1)<<3) + (lane&7);
                int bcol = dp*16 + ((lane>>4)<<3);
                ldsm4t(b0,b1,b2,b3, sV + (uint32_t)((brow*VLD + bcol)*2));
                mma16816(o[dp*2+0], a0,a1,a2,a3, b0,b1);
                mma16816(o[dp*2+1], a0,a1,a2,a3, b2,b3);
            }
        }
    }

    // ---- epilogue ----
    float inv0 = 1.f / l0, inv1 = 1.f / l1;
    size_t ob0 = (((size_t)b*S_+row0)*H_+h)*(size_t)DV_;
    size_t ob1 = (((size_t)b*S_+row1)*H_+h)*(size_t)DV_;
    int cb = (lane&3)*2;
    #pragma unroll
    for (int d = 0; d < 16; d++){
        *(float2*)(O + ob0 + d*8 + cb) = make_float2(o[d][0]*inv0, o[d][1]*inv0);
        *(float2*)(O + ob1 + d*8 + cb) = make_float2(o[d][2]*inv1, o[d][3]*inv1);
    }
    if ((lane & 3) == 0){
        LSE[((size_t)b*S_+row0)*H_ + h] = (m0r + __logf(l0)) * 1.4426950408889634f;
        LSE[((size_t)b*S_+row1)*H_ + h] = (m1r + __logf(l1)) * 1.4426950408889634f;
    }
}

extern "C" void kernel_launch(void* const* d_in, const int* in_sizes, int n_in,
                              void* d_out, int out_size) {
    const float* q_nope = (const float*)d_in[0];
    const float* q_pe   = (const float*)d_in[1];
    const float* k_nope = (const float*)d_in[2];
    const float* k_pe   = (const float*)d_in[3];
    const float* v      = (const float*)d_in[4];
    float* out = (float*)d_out;
    float* o_out   = out;
    float* lse_out = out + (size_t)B_*S_*H_*DV_;

    k_cs<<<(S_*32 + 255)/256, 256>>>();
    const int ntot = 2*NQ_ + NV_;
    k_prep<<<(ntot + 255)/256, 256>>>(q_nope, q_pe, k_nope, k_pe, v);

    cudaFuncSetAttribute(attn, cudaFuncAttributeMaxDynamicSharedMemorySize, SMEM_TOTAL);
    dim3 grid(S_/BM, B_*H_);
    attn<<<grid, 256, SMEM_TOTAL>>>(o_out, lse_out);
}

// round 5
// speedup vs baseline: 11.0634x; 2.4971x over previous
#include <cuda_runtime.h>
#include <cuda_fp16.h>
#include <cstdint>
#include <math.h>

#define B_  2
#define S_  2048
#define H_  16
#define DN_ 128
#define DR_ 64
#define D_  192
#define DV_ 128
#define BM  128
#define BN  64

#define KLD 200                 // halfs per K/Q row in smem
#define VLD 136                 // halfs per V row in smem
#define KSTG (64*KLD*2)         // 25600 B
#define VSTG (64*VLD*2)         // 17408 B
#define STG  (KSTG + VSTG)      // 43008 B
#define SMEM_TOTAL (2*STG)      // 86016 B  (Q staging reuses this region)

#define NQ_ (B_*S_*H_*D_)
#define NV_ (B_*S_*H_*DV_)

// ---- scratch (prepped fp16 operands) ----
__device__ __half g_Qh[(size_t)NQ_];
__device__ __half g_Kh[(size_t)NQ_];
__device__ __half g_Vh[(size_t)NV_];

// ---- helpers ----
__device__ __forceinline__ uint32_t smem_u32(const void* p){
    uint32_t a;
    asm("{ .reg .u64 t; cvta.to.shared.u64 t, %1; cvt.u32.u64 %0, t; }" : "=r"(a) : "l"(p));
    return a;
}
__device__ __forceinline__ void ldsm4(uint32_t& r0, uint32_t& r1, uint32_t& r2, uint32_t& r3, uint32_t a){
    asm volatile("ldmatrix.sync.aligned.m8n8.x4.shared.b16 {%0,%1,%2,%3},[%4];"
        : "=r"(r0),"=r"(r1),"=r"(r2),"=r"(r3) : "r"(a));
}
__device__ __forceinline__ void ldsm4t(uint32_t& r0, uint32_t& r1, uint32_t& r2, uint32_t& r3, uint32_t a){
    asm volatile("ldmatrix.sync.aligned.m8n8.x4.trans.shared.b16 {%0,%1,%2,%3},[%4];"
        : "=r"(r0),"=r"(r1),"=r"(r2),"=r"(r3) : "r"(a));
}
__device__ __forceinline__ void mma16816(float* c, uint32_t a0, uint32_t a1, uint32_t a2, uint32_t a3,
                                         uint32_t b0, uint32_t b1){
    asm volatile("mma.sync.aligned.m16n8k16.row.col.f32.f16.f16.f32 "
        "{%0,%1,%2,%3},{%4,%5,%6,%7},{%8,%9},{%0,%1,%2,%3};"
        : "+f"(c[0]),"+f"(c[1]),"+f"(c[2]),"+f"(c[3])
        : "r"(a0),"r"(a1),"r"(a2),"r"(a3),"r"(b0),"r"(b1));
}
__device__ __forceinline__ void cpasync16(uint32_t dst, const void* src){
    asm volatile("cp.async.cg.shared.global [%0], [%1], 16;" :: "r"(dst), "l"(src));
}
#define CP_COMMIT() asm volatile("cp.async.commit_group;" ::: "memory")
#define CP_WAIT0()  asm volatile("cp.async.wait_group 0;" ::: "memory")

// ---- prep: fp32 -> fp16 with RoPE; Q pre-scaled by sm_scale*log2(e) ----
__global__ void k_prep(const float* __restrict__ qn, const float* __restrict__ qp,
                       const float* __restrict__ kn, const float* __restrict__ kp,
                       const float* __restrict__ v){
    int u = blockIdx.x*256 + threadIdx.x;
    const int NQ8 = NQ_/8, NV8 = NV_/8;
    if (u < 2*NQ8){
        bool isQ = u < NQ8;
        int x = isQ ? u : u - NQ8;
        int g = x % 24;
        int h = (x/24) & 15;
        int s = (x/(24*16)) & 2047;
        int b =  x/(24*16*2048);
        int d = g*8;
        float vals[8];
        if (d < 128){
            const float* src = (isQ ? qn : kn) + (((size_t)(b*S_+s)*H_)+h)*(size_t)DN_ + d;
            float4 f0 = *(const float4*)src;
            float4 f1 = *(const float4*)(src+4);
            vals[0]=f0.x; vals[1]=f0.y; vals[2]=f0.z; vals[3]=f0.w;
            vals[4]=f1.x; vals[5]=f1.y; vals[6]=f1.z; vals[7]=f1.w;
        } else {
            int r = d - 128;
            const float* pe = isQ ? (qp + (((size_t)(b*S_+s)*H_)+h)*(size_t)DR_)
                                  : (kp + ((size_t)(b*S_+s))*(size_t)DR_);
            #pragma unroll
            for (int e = 0; e < 8; e++){
                int rr = r + e;
                int j = rr & 31;
                float inv = __expf(-(float)j * 0.28782313662425572f);  // ln(1e4)/32
                float ang = (float)s * inv;
                float sn, cs; sincosf(ang, &sn, &cs);
                vals[e] = (rr < 32) ? (pe[rr]*cs - pe[rr+32]*sn)
                                    : (pe[rr]*cs + pe[rr-32]*sn);
            }
        }
        const float sc = isQ ? (rsqrtf((float)(DN_+DR_)) * 1.4426950408889634f) : 1.0f;
        __half h8[8];
        #pragma unroll
        for (int e = 0; e < 8; e++) h8[e] = __float2half_rn(vals[e]*sc);
        __half* dst = (isQ ? g_Qh : g_Kh) + (size_t)x*8;
        *(uint4*)dst = *(uint4*)h8;
    } else {
        int x = u - 2*NQ8;
        if (x >= NV8) return;
        const float* src = v + (size_t)x*8;
        float4 f0 = *(const float4*)src;
        float4 f1 = *(const float4*)(src+4);
        __half h8[8];
        h8[0]=__float2half_rn(f0.x); h8[1]=__float2half_rn(f0.y);
        h8[2]=__float2half_rn(f0.z); h8[3]=__float2half_rn(f0.w);
        h8[4]=__float2half_rn(f1.x); h8[5]=__float2half_rn(f1.y);
        h8[6]=__float2half_rn(f1.z); h8[7]=__float2half_rn(f1.w);
        *(uint4*)(g_Vh + (size_t)x*8) = *(uint4*)h8;
    }
}

// ---- attention ----
__global__ __launch_bounds__(256)
void attn(float* __restrict__ O, float* __restrict__ LSE)
{
    extern __shared__ char smem[];
    __half* smh = (__half*)smem;
    uint32_t sb = smem_u32(smem);

    int tid  = threadIdx.x;
    int lane = tid & 31;
    int wid  = tid >> 5;
    int t  = (int)gridDim.x - 1 - (int)blockIdx.x;
    int bh = blockIdx.y;
    int b = bh >> 4, h = bh & 15;
    int m0 = t * BM;
    int nt = 2*t + 2;
    int rw0 = wid * 16;

    // ---- prologue: Q tile -> smem -> A-fragment registers ----
    for (int i = tid; i < 128*24; i += 256){
        int r = i / 24, c = (i % 24) * 8;
        *(uint4*)(smh + r*KLD + c) =
            *(const uint4*)(g_Qh + ((size_t)((b*S_+m0+r)*H_+h))*D_ + c);
    }
    __syncthreads();
    uint32_t qa[12][4];
    #pragma unroll
    for (int kc = 0; kc < 12; kc++)
        ldsm4(qa[kc][0], qa[kc][1], qa[kc][2], qa[kc][3],
              sb + (uint32_t)(((rw0 + (lane&15))*KLD + kc*16 + ((lane>>4)<<3))*2));
    __syncthreads();   // everyone done with Q smem; region becomes stage buffers

    const __half* kb = g_Kh + ((size_t)(b*S_)*H_ + h)*(size_t)D_;
    const __half* vb = g_Vh + ((size_t)(b*S_)*H_ + h)*(size_t)DV_;

    // issue stage 0
    {
        uint32_t sK = sb, sV = sb + KSTG;
        for (int i = tid; i < 64*24; i += 256){
            int r = i / 24, c = i % 24;
            cpasync16(sK + (uint32_t)(r*KLD*2 + c*16), kb + (size_t)r*H_*D_ + c*8);
        }
        for (int i = tid; i < 64*16; i += 256){
            int r = i / 16, c = i % 16;
            cpasync16(sV + (uint32_t)(r*VLD*2 + c*16), vb + (size_t)r*H_*DV_ + c*8);
        }
        CP_COMMIT();
    }

    float o[16][4];
    #pragma unroll
    for (int d = 0; d < 16; d++){ o[d][0]=0.f; o[d][1]=0.f; o[d][2]=0.f; o[d][3]=0.f; }
    float m0r = -INFINITY, m1r = -INFINITY, l0 = 0.f, l1 = 0.f;
    int row0 = m0 + rw0 + (lane >> 2);
    int row1 = row0 + 8;

    for (int j = 0; j < nt; j++){
        CP_WAIT0();
        __syncthreads();   // stage j ready; all warps done with buffer (j+1)&1

        if (j + 1 < nt){
            int n1 = (j+1) * BN;
            uint32_t sK = sb + ((j+1)&1)*STG, sV = sK + KSTG;
            const __half* kr = kb + (size_t)n1*H_*D_;
            const __half* vr = vb + (size_t)n1*H_*DV_;
            for (int i = tid; i < 64*24; i += 256){
                int r = i / 24, c = i % 24;
                cpasync16(sK + (uint32_t)(r*KLD*2 + c*16), kr + (size_t)r*H_*D_ + c*8);
            }
            for (int i = tid; i < 64*16; i += 256){
                int r = i / 16, c = i % 16;
                cpasync16(sV + (uint32_t)(r*VLD*2 + c*16), vr + (size_t)r*H_*DV_ + c*8);
            }
            CP_COMMIT();
        }

        uint32_t sK = sb + (j&1)*STG, sV = sK + KSTG;
        int n0 = j * BN;

        // ---- S = Q K^T ----
        float c_[8][4];
        #pragma unroll
        for (int q = 0; q < 8; q++){ c_[q][0]=0.f; c_[q][1]=0.f; c_[q][2]=0.f; c_[q][3]=0.f; }
        #pragma unroll
        for (int kc = 0; kc < 12; kc++){
            #pragma unroll
            for (int np = 0; np < 4; np++){
                uint32_t b0,b1,b2,b3;
                int brow = np*16 + ((lane>>4)<<3) + (lane&7);
                int bcol = kc*16 + (((lane>>3)&1)<<3);
                ldsm4(b0,b1,b2,b3, sK + (uint32_t)((brow*KLD + bcol)*2));
                mma16816(c_[np*2+0], qa[kc][0],qa[kc][1],qa[kc][2],qa[kc][3], b0,b1);
                mma16816(c_[np*2+1], qa[kc][0],qa[kc][1],qa[kc][2],qa[kc][3], b2,b3);
            }
        }

        // ---- causal mask (diagonal block only) ----
        if (j >= 2*t){
            int colb = n0 + (lane&3)*2;
            #pragma unroll
            for (int q = 0; q < 8; q++){
                int c0 = colb + q*8, c1 = c0 + 1;
                if (c0 > row0) c_[q][0] = -INFINITY;
                if (c1 > row0) c_[q][1] = -INFINITY;
                if (c0 > row1) c_[q][2] = -INFINITY;
                if (c1 > row1) c_[q][3] = -INFINITY;
            }
        }

        // ---- online softmax (base-2; log2e folded into Q scale) ----
        float mx0 = -INFINITY, mx1 = -INFINITY;
        #pragma unroll
        for (int q = 0; q < 8; q++){
            mx0 = fmaxf(mx0, fmaxf(c_[q][0], c_[q][1]));
            mx1 = fmaxf(mx1, fmaxf(c_[q][2], c_[q][3]));
        }
        mx0 = fmaxf(mx0, __shfl_xor_sync(0xffffffffu, mx0, 1));
        mx0 = fmaxf(mx0, __shfl_xor_sync(0xffffffffu, mx0, 2));
        mx1 = fmaxf(mx1, __shfl_xor_sync(0xffffffffu, mx1, 1));
        mx1 = fmaxf(mx1, __shfl_xor_sync(0xffffffffu, mx1, 2));
        float mn0 = fmaxf(m0r, mx0), mn1 = fmaxf(m1r, mx1);
        float corr0 = exp2f(m0r - mn0), corr1 = exp2f(m1r - mn1);
        m0r = mn0; m1r = mn1;

        float sum0 = 0.f, sum1 = 0.f;
        #pragma unroll
        for (int q = 0; q < 8; q++){
            c_[q][0] = exp2f(c_[q][0] - mn0);
            c_[q][1] = exp2f(c_[q][1] - mn0);
            c_[q][2] = exp2f(c_[q][2] - mn1);
            c_[q][3] = exp2f(c_[q][3] - mn1);
            sum0 += c_[q][0] + c_[q][1];
            sum1 += c_[q][2] + c_[q][3];
        }
        sum0 += __shfl_xor_sync(0xffffffffu, sum0, 1);
        sum0 += __shfl_xor_sync(0xffffffffu, sum0, 2);
        sum1 += __shfl_xor_sync(0xffffffffu, sum1, 1);
        sum1 += __shfl_xor_sync(0xffffffffu, sum1, 2);
        l0 = l0*corr0 + sum0;
        l1 = l1*corr1 + sum1;

        #pragma unroll
        for (int d = 0; d < 16; d++){
            o[d][0] *= corr0; o[d][1] *= corr0;
            o[d][2] *= corr1; o[d][3] *= corr1;
        }

        // ---- O += P V : P fragments straight from registers ----
        #pragma unroll
        for (int kc = 0; kc < 4; kc++){
            __half2 pa0 = __floats2half2_rn(c_[2*kc][0],   c_[2*kc][1]);
            __half2 pa1 = __floats2half2_rn(c_[2*kc][2],   c_[2*kc][3]);
            __half2 pa2 = __floats2half2_rn(c_[2*kc+1][0], c_[2*kc+1][1]);
            __half2 pa3 = __floats2half2_rn(c_[2*kc+1][2], c_[2*kc+1][3]);
            uint32_t u0 = *(uint32_t*)&pa0, u1 = *(uint32_t*)&pa1;
            uint32_t u2 = *(uint32_t*)&pa2, u3 = *(uint32_t*)&pa3;
            #pragma unroll
            for (int dp = 0; dp < 8; dp++){
                uint32_t b0,b1,b2,b3;
                int brow = kc*16 + (((lane>>3)&1)<<3) + (lane&7);
                int bcol = dp*16 + ((lane>>4)<<3);
                ldsm4t(b0,b1,b2,b3, sV + (uint32_t)((brow*VLD + bcol)*2));
                mma16816(o[dp*2+0], u0,u1,u2,u3, b0,b1);
                mma16816(o[dp*2+1], u0,u1,u2,u3, b2,b3);
            }
        }
    }

    // ---- epilogue ----
    float inv0 = 1.f / l0, inv1 = 1.f / l1;
    size_t ob0 = (((size_t)b*S_+row0)*H_+h)*(size_t)DV_;
    size_t ob1 = (((size_t)b*S_+row1)*H_+h)*(size_t)DV_;
    int cb = (lane&3)*2;
    #pragma unroll
    for (int d = 0; d < 16; d++){
        *(float2*)(O + ob0 + d*8 + cb) = make_float2(o[d][0]*inv0, o[d][1]*inv0);
        *(float2*)(O + ob1 + d*8 + cb) = make_float2(o[d][2]*inv1, o[d][3]*inv1);
    }
    if ((lane & 3) == 0){
        LSE[((size_t)b*S_+row0)*H_ + h] = m0r + log2f(l0);
        LSE[((size_t)b*S_+row1)*H_ + h] = m1r + log2f(l1);
    }
}

extern "C" void kernel_launch(void* const* d_in, const int* in_sizes, int n_in,
                              void* d_out, int out_size) {
    const float* q_nope = (const float*)d_in[0];
    const float* q_pe   = (const float*)d_in[1];
    const float* k_nope = (const float*)d_in[2];
    const float* k_pe   = (const float*)d_in[3];
    const float* v      = (const float*)d_in[4];
    float* out = (float*)d_out;
    float* o_out   = out;
    float* lse_out = out + (size_t)B_*S_*H_*DV_;

    const int nunits = 2*(NQ_/8) + NV_/8;
    k_prep<<<(nunits + 255)/256, 256>>>(q_nope, q_pe, k_nope, k_pe, v);

    cudaFuncSetAttribute(attn, cudaFuncAttributeMaxDynamicSharedMemorySize, SMEM_TOTAL);
    dim3 grid(S_/BM, B_*H_);
    attn<<<grid, 256, SMEM_TOTAL>>>(o_out, lse_out);
}

// round 6
// speedup vs baseline: 12.4057x; 1.1213x over previous
#include <cuda_runtime.h>
#include <cuda_fp16.h>
#include <cstdint>
#include <math.h>

#define B_  2
#define S_  2048
#define H_  16
#define DN_ 128
#define DR_ 64
#define D_  192
#define DV_ 128
#define BM  64
#define BN  64
#define NWARP 4
#define NTHR  128

#define KLD 200                 // halfs per K/Q row in smem
#define VLD 136                 // halfs per V row in smem
#define KSTG (64*KLD*2)         // 25600 B
#define VSTG (64*VLD*2)         // 17408 B
#define STG  (KSTG + VSTG)      // 43008 B
#define SMEM_TOTAL (2*STG)      // 86016 B  (Q staging reuses this region)

#define NQ_ (B_*S_*H_*D_)
#define NV_ (B_*S_*H_*DV_)

// ---- scratch (prepped fp16 operands) ----
__device__ __half g_Qh[(size_t)NQ_];
__device__ __half g_Kh[(size_t)NQ_];
__device__ __half g_Vh[(size_t)NV_];

// ---- helpers ----
__device__ __forceinline__ uint32_t smem_u32(const void* p){
    uint32_t a;
    asm("{ .reg .u64 t; cvta.to.shared.u64 t, %1; cvt.u32.u64 %0, t; }" : "=r"(a) : "l"(p));
    return a;
}
__device__ __forceinline__ float ex2(float x){
    float y; asm("ex2.approx.f32 %0, %1;" : "=f"(y) : "f"(x)); return y;
}
__device__ __forceinline__ void ldsm4(uint32_t& r0, uint32_t& r1, uint32_t& r2, uint32_t& r3, uint32_t a){
    asm volatile("ldmatrix.sync.aligned.m8n8.x4.shared.b16 {%0,%1,%2,%3},[%4];"
        : "=r"(r0),"=r"(r1),"=r"(r2),"=r"(r3) : "r"(a));
}
__device__ __forceinline__ void ldsm4t(uint32_t& r0, uint32_t& r1, uint32_t& r2, uint32_t& r3, uint32_t a){
    asm volatile("ldmatrix.sync.aligned.m8n8.x4.trans.shared.b16 {%0,%1,%2,%3},[%4];"
        : "=r"(r0),"=r"(r1),"=r"(r2),"=r"(r3) : "r"(a));
}
__device__ __forceinline__ void mma16816(float* c, uint32_t a0, uint32_t a1, uint32_t a2, uint32_t a3,
                                         uint32_t b0, uint32_t b1){
    asm volatile("mma.sync.aligned.m16n8k16.row.col.f32.f16.f16.f32 "
        "{%0,%1,%2,%3},{%4,%5,%6,%7},{%8,%9},{%0,%1,%2,%3};"
        : "+f"(c[0]),"+f"(c[1]),"+f"(c[2]),"+f"(c[3])
        : "r"(a0),"r"(a1),"r"(a2),"r"(a3),"r"(b0),"r"(b1));
}
__device__ __forceinline__ void cpasync16(uint32_t dst, const void* src){
    asm volatile("cp.async.cg.shared.global [%0], [%1], 16;" :: "r"(dst), "l"(src));
}
#define CP_COMMIT() asm volatile("cp.async.commit_group;" ::: "memory")
#define CP_WAIT0()  asm volatile("cp.async.wait_group 0;" ::: "memory")

// ---- prep: fp32 -> fp16 with RoPE; Q pre-scaled by sm_scale*log2(e) ----
__global__ void k_prep(const float* __restrict__ qn, const float* __restrict__ qp,
                       const float* __restrict__ kn, const float* __restrict__ kp,
                       const float* __restrict__ v){
    int u = blockIdx.x*256 + threadIdx.x;
    const int NQ8 = NQ_/8, NV8 = NV_/8;
    if (u < 2*NQ8){
        bool isQ = u < NQ8;
        int x = isQ ? u : u - NQ8;
        int g = x % 24;
        int h = (x/24) & 15;
        int s = (x/(24*16)) & 2047;
        int b =  x/(24*16*2048);
        int d = g*8;
        float vals[8];
        if (d < 128){
            const float* src = (isQ ? qn : kn) + (((size_t)(b*S_+s)*H_)+h)*(size_t)DN_ + d;
            float4 f0 = *(const float4*)src;
            float4 f1 = *(const float4*)(src+4);
            vals[0]=f0.x; vals[1]=f0.y; vals[2]=f0.z; vals[3]=f0.w;
            vals[4]=f1.x; vals[5]=f1.y; vals[6]=f1.z; vals[7]=f1.w;
        } else {
            int r = d - 128;
            const float* pe = isQ ? (qp + (((size_t)(b*S_+s)*H_)+h)*(size_t)DR_)
                                  : (kp + ((size_t)(b*S_+s))*(size_t)DR_);
            #pragma unroll
            for (int e = 0; e < 8; e++){
                int rr = r + e;
                int j = rr & 31;
                float inv = __expf(-(float)j * 0.28782313662425572f);  // ln(1e4)/32
                float ang = (float)s * inv;
                float sn, cs; sincosf(ang, &sn, &cs);
                vals[e] = (rr < 32) ? (pe[rr]*cs - pe[rr+32]*sn)
                                    : (pe[rr]*cs + pe[rr-32]*sn);
            }
        }
        const float sc = isQ ? (rsqrtf((float)(DN_+DR_)) * 1.4426950408889634f) : 1.0f;
        __half h8[8];
        #pragma unroll
        for (int e = 0; e < 8; e++) h8[e] = __float2half_rn(vals[e]*sc);
        __half* dst = (isQ ? g_Qh : g_Kh) + (size_t)x*8;
        *(uint4*)dst = *(uint4*)h8;
    } else {
        int x = u - 2*NQ8;
        if (x >= NV8) return;
        const float* src = v + (size_t)x*8;
        float4 f0 = *(const float4*)src;
        float4 f1 = *(const float4*)(src+4);
        __half h8[8];
        h8[0]=__float2half_rn(f0.x); h8[1]=__float2half_rn(f0.y);
        h8[2]=__float2half_rn(f0.z); h8[3]=__float2half_rn(f0.w);
        h8[4]=__float2half_rn(f1.x); h8[5]=__float2half_rn(f1.y);
        h8[6]=__float2half_rn(f1.z); h8[7]=__float2half_rn(f1.w);
        *(uint4*)(g_Vh + (size_t)x*8) = *(uint4*)h8;
    }
}

// ---- attention: BM=64, 4 warps, 2 CTAs/SM ----
__global__ __launch_bounds__(NTHR, 2)
void attn(float* __restrict__ O, float* __restrict__ LSE)
{
    extern __shared__ char smem[];
    __half* smh = (__half*)smem;
    uint32_t sb = smem_u32(smem);

    int tid  = threadIdx.x;
    int lane = tid & 31;
    int wid  = tid >> 5;
    int t  = (int)gridDim.x - 1 - (int)blockIdx.x;
    int bh = blockIdx.y;
    int b = bh >> 4, h = bh & 15;
    int m0 = t * BM;
    int nt = t + 1;
    int rw0 = wid * 16;

    // ---- prologue: Q tile -> smem -> A-fragment registers ----
    for (int i = tid; i < 64*24; i += NTHR){
        int r = i / 24, c = (i % 24) * 8;
        *(uint4*)(smh + r*KLD + c) =
            *(const uint4*)(g_Qh + ((size_t)((b*S_+m0+r)*H_+h))*D_ + c);
    }
    __syncthreads();
    uint32_t qa[12][4];
    #pragma unroll
    for (int kc = 0; kc < 12; kc++)
        ldsm4(qa[kc][0], qa[kc][1], qa[kc][2], qa[kc][3],
              sb + (uint32_t)(((rw0 + (lane&15))*KLD + kc*16 + ((lane>>4)<<3))*2));
    __syncthreads();   // Q smem region becomes stage buffers

    const __half* kb = g_Kh + ((size_t)(b*S_)*H_ + h)*(size_t)D_;
    const __half* vb = g_Vh + ((size_t)(b*S_)*H_ + h)*(size_t)DV_;

    // issue stage 0
    {
        uint32_t sK = sb, sV = sb + KSTG;
        for (int i = tid; i < 64*24; i += NTHR){
            int r = i / 24, c = i % 24;
            cpasync16(sK + (uint32_t)(r*KLD*2 + c*16), kb + (size_t)r*H_*D_ + c*8);
        }
        for (int i = tid; i < 64*16; i += NTHR){
            int r = i / 16, c = i % 16;
            cpasync16(sV + (uint32_t)(r*VLD*2 + c*16), vb + (size_t)r*H_*DV_ + c*8);
        }
        CP_COMMIT();
    }

    float o[16][4];
    #pragma unroll
    for (int d = 0; d < 16; d++){ o[d][0]=0.f; o[d][1]=0.f; o[d][2]=0.f; o[d][3]=0.f; }
    float m0r = -INFINITY, m1r = -INFINITY, l0 = 0.f, l1 = 0.f;
    int row0 = m0 + rw0 + (lane >> 2);
    int row1 = row0 + 8;

    for (int j = 0; j < nt; j++){
        CP_WAIT0();
        __syncthreads();   // stage j ready; all warps done with buffer (j+1)&1

        if (j + 1 < nt){
            int n1 = (j+1) * BN;
            uint32_t sK = sb + ((j+1)&1)*STG, sV = sK + KSTG;
            const __half* kr = kb + (size_t)n1*H_*D_;
            const __half* vr = vb + (size_t)n1*H_*DV_;
            for (int i = tid; i < 64*24; i += NTHR){
                int r = i / 24, c = i % 24;
                cpasync16(sK + (uint32_t)(r*KLD*2 + c*16), kr + (size_t)r*H_*D_ + c*8);
            }
            for (int i = tid; i < 64*16; i += NTHR){
                int r = i / 16, c = i % 16;
                cpasync16(sV + (uint32_t)(r*VLD*2 + c*16), vr + (size_t)r*H_*DV_ + c*8);
            }
            CP_COMMIT();
        }

        uint32_t sK = sb + (j&1)*STG, sV = sK + KSTG;
        int n0 = j * BN;

        // ---- S = Q K^T ----
        float c_[8][4];
        #pragma unroll
        for (int q = 0; q < 8; q++){ c_[q][0]=0.f; c_[q][1]=0.f; c_[q][2]=0.f; c_[q][3]=0.f; }
        #pragma unroll
        for (int kc = 0; kc < 12; kc++){
            #pragma unroll
            for (int np = 0; np < 4; np++){
                uint32_t b0,b1,b2,b3;
                int brow = np*16 + ((lane>>4)<<3) + (lane&7);
                int bcol = kc*16 + (((lane>>3)&1)<<3);
                ldsm4(b0,b1,b2,b3, sK + (uint32_t)((brow*KLD + bcol)*2));
                mma16816(c_[np*2+0], qa[kc][0],qa[kc][1],qa[kc][2],qa[kc][3], b0,b1);
                mma16816(c_[np*2+1], qa[kc][0],qa[kc][1],qa[kc][2],qa[kc][3], b2,b3);
            }
        }

        // ---- causal mask (diagonal tile only) ----
        if (j == t){
            int colb = n0 + (lane&3)*2;
            #pragma unroll
            for (int q = 0; q < 8; q++){
                int c0 = colb + q*8, c1 = c0 + 1;
                if (c0 > row0) c_[q][0] = -INFINITY;
                if (c1 > row0) c_[q][1] = -INFINITY;
                if (c0 > row1) c_[q][2] = -INFINITY;
                if (c1 > row1) c_[q][3] = -INFINITY;
            }
        }

        // ---- online softmax (base-2; log2e folded into Q scale) ----
        float mx0 = -INFINITY, mx1 = -INFINITY;
        #pragma unroll
        for (int q = 0; q < 8; q++){
            mx0 = fmaxf(mx0, fmaxf(c_[q][0], c_[q][1]));
            mx1 = fmaxf(mx1, fmaxf(c_[q][2], c_[q][3]));
        }
        mx0 = fmaxf(mx0, __shfl_xor_sync(0xffffffffu, mx0, 1));
        mx0 = fmaxf(mx0, __shfl_xor_sync(0xffffffffu, mx0, 2));
        mx1 = fmaxf(mx1, __shfl_xor_sync(0xffffffffu, mx1, 1));
        mx1 = fmaxf(mx1, __shfl_xor_sync(0xffffffffu, mx1, 2));
        float mn0 = fmaxf(m0r, mx0), mn1 = fmaxf(m1r, mx1);
        float corr0 = ex2(m0r - mn0), corr1 = ex2(m1r - mn1);
        m0r = mn0; m1r = mn1;

        float sum0 = 0.f, sum1 = 0.f;
        #pragma unroll
        for (int q = 0; q < 8; q++){
            c_[q][0] = ex2(c_[q][0] - mn0);
            c_[q][1] = ex2(c_[q][1] - mn0);
            c_[q][2] = ex2(c_[q][2] - mn1);
            c_[q][3] = ex2(c_[q][3] - mn1);
            sum0 += c_[q][0] + c_[q][1];
            sum1 += c_[q][2] + c_[q][3];
        }
        sum0 += __shfl_xor_sync(0xffffffffu, sum0, 1);
        sum0 += __shfl_xor_sync(0xffffffffu, sum0, 2);
        sum1 += __shfl_xor_sync(0xffffffffu, sum1, 1);
        sum1 += __shfl_xor_sync(0xffffffffu, sum1, 2);
        l0 = l0*corr0 + sum0;
        l1 = l1*corr1 + sum1;

        #pragma unroll
        for (int d = 0; d < 16; d++){
            o[d][0] *= corr0; o[d][1] *= corr0;
            o[d][2] *= corr1; o[d][3] *= corr1;
        }

        // ---- O += P V : P fragments straight from registers ----
        #pragma unroll
        for (int kc = 0; kc < 4; kc++){
            __half2 pa0 = __floats2half2_rn(c_[2*kc][0],   c_[2*kc][1]);
            __half2 pa1 = __floats2half2_rn(c_[2*kc][2],   c_[2*kc][3]);
            __half2 pa2 = __floats2half2_rn(c_[2*kc+1][0], c_[2*kc+1][1]);
            __half2 pa3 = __floats2half2_rn(c_[2*kc+1][2], c_[2*kc+1][3]);
            uint32_t u0 = *(uint32_t*)&pa0, u1 = *(uint32_t*)&pa1;
            uint32_t u2 = *(uint32_t*)&pa2, u3 = *(uint32_t*)&pa3;
            #pragma unroll
            for (int dp = 0; dp < 8; dp++){
                uint32_t b0,b1,b2,b3;
                int brow = kc*16 + (((lane>>3)&1)<<3) + (lane&7);
                int bcol = dp*16 + ((lane>>4)<<3);
                ldsm4t(b0,b1,b2,b3, sV + (uint32_t)((brow*VLD + bcol)*2));
                mma16816(o[dp*2+0], u0,u1,u2,u3, b0,b1);
                mma16816(o[dp*2+1], u0,u1,u2,u3, b2,b3);
            }
        }
    }

    // ---- epilogue ----
    float inv0 = 1.f / l0, inv1 = 1.f / l1;
    size_t ob0 = (((size_t)b*S_+row0)*H_+h)*(size_t)DV_;
    size_t ob1 = (((size_t)b*S_+row1)*H_+h)*(size_t)DV_;
    int cb = (lane&3)*2;
    #pragma unroll
    for (int d = 0; d < 16; d++){
        *(float2*)(O + ob0 + d*8 + cb) = make_float2(o[d][0]*inv0, o[d][1]*inv0);
        *(float2*)(O + ob1 + d*8 + cb) = make_float2(o[d][2]*inv1, o[d][3]*inv1);
    }
    if ((lane & 3) == 0){
        LSE[((size_t)b*S_+row0)*H_ + h] = m0r + log2f(l0);
        LSE[((size_t)b*S_+row1)*H_ + h] = m1r + log2f(l1);
    }
}

extern "C" void kernel_launch(void* const* d_in, const int* in_sizes, int n_in,
                              void* d_out, int out_size) {
    const float* q_nope = (const float*)d_in[0];
    const float* q_pe   = (const float*)d_in[1];
    const float* k_nope = (const float*)d_in[2];
    const float* k_pe   = (const float*)d_in[3];
    const float* v      = (const float*)d_in[4];
    float* out = (float*)d_out;
    float* o_out   = out;
    float* lse_out = out + (size_t)B_*S_*H_*DV_;

    const int nunits = 2*(NQ_/8) + NV_/8;
    k_prep<<<(nunits + 255)/256, 256>>>(q_nope, q_pe, k_nope, k_pe, v);

    cudaFuncSetAttribute(attn, cudaFuncAttributeMaxDynamicSharedMemorySize, SMEM_TOTAL);
    dim3 grid(S_/BM, B_*H_);
    attn<<<grid, NTHR, SMEM_TOTAL>>>(o_out, lse_out);
}